// round 5
// baseline (speedup 1.0000x reference)
#include <cuda_runtime.h>
#include <cuda_bf16.h>
#include <math.h>
#include <stdint.h>

#define N_TOK 2048
#define C_DIM 1024
#define E_NUM 32
#define TOPK  4
#define H_RT  512
#define HS_SH 1024
#define NPAIR (N_TOK * TOPK)   // 8192

// ---------------------------------------------------------------------------
// Baseline-ISA helpers (ptxas target is sm_103 — no tcgen05 available)
// ---------------------------------------------------------------------------
__device__ __forceinline__ uint32_t smem_to_u32(const void* p) {
    uint32_t a;
    asm("{ .reg .u64 t; cvta.to.shared.u64 t, %1; cvt.u32.u64 %0, t; }" : "=r"(a) : "l"(p));
    return a;
}
__device__ __forceinline__ void cp_async16(uint32_t smem_dst, const void* gsrc) {
    asm volatile("cp.async.cg.shared.global [%0], [%1], 16;"
                 :: "r"(smem_dst), "l"(gsrc) : "memory");
}
__device__ __forceinline__ void cp_commit() {
    asm volatile("cp.async.commit_group;" ::: "memory");
}
template <int N>
__device__ __forceinline__ void cp_wait() {
    asm volatile("cp.async.wait_group %0;" :: "n"(N) : "memory");
}
__device__ __forceinline__ void ldsm_x4(uint32_t& r0, uint32_t& r1, uint32_t& r2,
                                        uint32_t& r3, uint32_t addr) {
    asm volatile("ldmatrix.sync.aligned.m8n8.x4.shared.b16 {%0,%1,%2,%3}, [%4];"
                 : "=r"(r0), "=r"(r1), "=r"(r2), "=r"(r3) : "r"(addr));
}
__device__ __forceinline__ void ldsm_x4_t(uint32_t& r0, uint32_t& r1, uint32_t& r2,
                                          uint32_t& r3, uint32_t addr) {
    asm volatile("ldmatrix.sync.aligned.m8n8.x4.trans.shared.b16 {%0,%1,%2,%3}, [%4];"
                 : "=r"(r0), "=r"(r1), "=r"(r2), "=r"(r3) : "r"(addr));
}
__device__ __forceinline__ void mma16816(float* c, const uint32_t* a, const uint32_t* b) {
    asm volatile("mma.sync.aligned.m16n8k16.row.col.f32.bf16.bf16.f32 "
                 "{%0,%1,%2,%3}, {%4,%5,%6,%7}, {%8,%9}, {%0,%1,%2,%3};"
                 : "+f"(c[0]), "+f"(c[1]), "+f"(c[2]), "+f"(c[3])
                 : "r"(a[0]), "r"(a[1]), "r"(a[2]), "r"(a[3]), "r"(b[0]), "r"(b[1]));
}

// ---------------------------------------------------------------------------
// Scratch (weights kept in native [K,N] layout; only dtype-split, no transpose)
// ---------------------------------------------------------------------------
__device__ __nv_bfloat16 g_x_hi [N_TOK * C_DIM];
__device__ __nv_bfloat16 g_x_lo [N_TOK * C_DIM];
__device__ float         g_u_sh [N_TOK * 2 * HS_SH];
__device__ __nv_bfloat16 g_hs_hi[N_TOK * HS_SH];
__device__ __nv_bfloat16 g_hs_lo[N_TOK * HS_SH];
__device__ float         g_u_rt [NPAIR * 2 * H_RT];
__device__ __nv_bfloat16 g_h_hi [NPAIR * H_RT];
__device__ __nv_bfloat16 g_h_lo [NPAIR * H_RT];
__device__ float         g_y_rt [NPAIR * C_DIM];
__device__ __nv_bfloat16 g_sgw_hi[C_DIM * 2 * HS_SH];
__device__ __nv_bfloat16 g_sgw_lo[C_DIM * 2 * HS_SH];
__device__ __nv_bfloat16 g_sdw_hi[HS_SH * C_DIM];
__device__ __nv_bfloat16 g_sdw_lo[HS_SH * C_DIM];
__device__ __nv_bfloat16 g_egw_hi[E_NUM * C_DIM * 2 * H_RT];
__device__ __nv_bfloat16 g_egw_lo[E_NUM * C_DIM * 2 * H_RT];
__device__ __nv_bfloat16 g_edw_hi[E_NUM * H_RT * C_DIM];
__device__ __nv_bfloat16 g_edw_lo[E_NUM * H_RT * C_DIM];
__device__ int   d_cnt [E_NUM];
__device__ int   d_slot[E_NUM * N_TOK];
__device__ float d_wt  [NPAIR];

__global__ void zero_cnt_kernel() {
    if (threadIdx.x < E_NUM) d_cnt[threadIdx.x] = 0;
}

// ---------------------------------------------------------------------------
// Gating (verified correct since R1)
// ---------------------------------------------------------------------------
__global__ void gate_kernel(const float* __restrict__ x,
                            const float* __restrict__ gw,
                            const float* __restrict__ gb) {
    int n = blockIdx.x;
    int e = threadIdx.x;
    const float* xr = x + n * C_DIM;
    float acc = 0.f;
#pragma unroll 8
    for (int c = 0; c < C_DIM; c++)
        acc = fmaf(xr[c], gw[c * E_NUM + e], acc);
    float s = 1.f / (1.f + expf(-acc));
    __shared__ float sc[E_NUM];
    sc[e] = s;
    __syncwarp();
    if (e == 0) {
        float sb[E_NUM];
#pragma unroll
        for (int i = 0; i < E_NUM; i++) sb[i] = sc[i] + gb[i];
        int idx[TOPK];
        float wsum = 0.f;
#pragma unroll
        for (int k = 0; k < TOPK; k++) {
            int best = 0; float bv = -1e30f;
            for (int i = 0; i < E_NUM; i++)
                if (sb[i] > bv) { bv = sb[i]; best = i; }
            sb[best] = -2e30f;
            idx[k] = best;
            wsum += sc[best];
        }
        float inv = 1.f / wsum;
#pragma unroll
        for (int k = 0; k < TOPK; k++) {
            int ee = idx[k];
            d_wt[n * TOPK + k] = sc[ee] * inv;
            int pos = atomicAdd(&d_cnt[ee], 1);
            d_slot[ee * N_TOK + pos] = n * TOPK + k;
        }
    }
}

// ---------------------------------------------------------------------------
// Streaming fp32 -> bf16 hi/lo split (coalesced float4 -> 2x 8B)
// ---------------------------------------------------------------------------
__global__ void split_kernel(const float4* __restrict__ src,
                             uint2* __restrict__ hi, uint2* __restrict__ lo) {
    int i = blockIdx.x * 256 + threadIdx.x;
    float4 v = src[i];
    __nv_bfloat16 h0 = __float2bfloat16_rn(v.x);
    __nv_bfloat16 h1 = __float2bfloat16_rn(v.y);
    __nv_bfloat16 h2 = __float2bfloat16_rn(v.z);
    __nv_bfloat16 h3 = __float2bfloat16_rn(v.w);
    __nv_bfloat16 l0 = __float2bfloat16_rn(v.x - __bfloat162float(h0));
    __nv_bfloat16 l1 = __float2bfloat16_rn(v.y - __bfloat162float(h1));
    __nv_bfloat16 l2 = __float2bfloat16_rn(v.z - __bfloat162float(h2));
    __nv_bfloat16 l3 = __float2bfloat16_rn(v.w - __bfloat162float(h3));
    __nv_bfloat162 hp0(h0, h1), hp1(h2, h3), lp0(l0, l1), lp1(l2, l3);
    hi[i] = make_uint2(*(uint32_t*)&hp0, *(uint32_t*)&hp1);
    lo[i] = make_uint2(*(uint32_t*)&lp0, *(uint32_t*)&lp1);
}

// ---------------------------------------------------------------------------
// bf16x3 GEMM via mma.sync.m16n8k16, B read from native [K,ND] via ldmatrix.trans.
//   C[M rows, LDC] (fp32) = (Ahi+Alo)[M,K] @ (Bhi+Blo)[K,ND] tile at n0
// 3 phases: (Ahi,Bhi), (Ahi,Blo), (Alo,Bhi). Block 128x128, BK=64, 8 warps
// (2M x 4N, 64x32 per warp), double-buffered cp.async.
// GATHER: A rows / C rows via per-expert slot lists (blockIdx.z = expert).
// ---------------------------------------------------------------------------
#define APAD 72    // A row stride (bf16): 144B = 9*16B -> conflict-free
#define BPAD 136   // B row stride (bf16): 272B = 17*16B -> conflict-free

template <int K_DIM, int ND, int LDC, int ASHIFT, bool GATHER>
__global__ void __launch_bounds__(256) mma_gemm(
    const __nv_bfloat16* __restrict__ Ahi, const __nv_bfloat16* __restrict__ Alo,
    const __nv_bfloat16* __restrict__ Bhi, const __nv_bfloat16* __restrict__ Blo,
    float* __restrict__ C)
{
    extern __shared__ __align__(16) char smem[];
    __nv_bfloat16* sA = (__nv_bfloat16*)smem;                    // 2 x 128 x APAD
    __nv_bfloat16* sB = (__nv_bfloat16*)(smem + 2 * 128 * APAD * 2);  // 2 x 64 x BPAD
    int* slots = (int*)(smem + 2 * 128 * APAD * 2 + 2 * 64 * BPAD * 2);

    const int CPP = K_DIM / 64;        // chunks per phase
    const int NC  = 3 * CPP;

    int t    = threadIdx.x;
    int wid  = t >> 5, lane = t & 31;
    int e    = GATHER ? blockIdx.z : 0;
    int cnt  = GATHER ? d_cnt[e] : (1 << 30);
    int m0   = blockIdx.x * 128;
    if (GATHER && m0 >= cnt) return;
    int n0   = blockIdx.y * 128;

    if (GATHER && t < 128) {
        int m = m0 + t;
        slots[t] = (m < cnt) ? d_slot[e * N_TOK + m] : 0;
    }
    __syncthreads();

    // --- A loader: row = t>>1 (0..127), 4 chunks of 8 els at k = ((t&1)*4+i)*8
    int a_row = t >> 1, a_c0 = (t & 1) * 4;
    int ga = GATHER ? (slots[a_row] >> ASHIFT) : (m0 + a_row);
    long aoff = (long)ga * K_DIM + a_c0 * 8;
    uint32_t sa_t = (uint32_t)(a_row * APAD + a_c0 * 8) * 2;

    // --- B loader: k-row = t>>2 (0..63), 4 chunks at n = ((t&3)*4+i)*8
    int b_row = t >> 2, b_c0 = (t & 3) * 4;
    long boff = (long)e * K_DIM * ND + (long)b_row * ND + n0 + b_c0 * 8;
    uint32_t sb_t = (uint32_t)(b_row * BPAD + b_c0 * 8) * 2;

    uint32_t sA_u = smem_to_u32(sA), sB_u = smem_to_u32(sB);
    const uint32_t ABUF = 128 * APAD * 2, BBUF = 64 * BPAD * 2;

    // --- mma geometry
    int wm = (wid >> 2) * 64;
    int wn = (wid & 3) * 32;
    float acc[4][4][4];
#pragma unroll
    for (int i = 0; i < 4; i++)
#pragma unroll
        for (int j = 0; j < 4; j++)
#pragma unroll
            for (int r = 0; r < 4; r++) acc[i][j][r] = 0.f;

    int lrow = lane & 15, lsel = lane >> 4;         // A ldmatrix
    int bg = lane >> 3, bL = lane & 7;              // B ldmatrix.trans

    auto issue = [&](int ch, int buf) {
        int phase = ch / CPP;
        long kc = (long)(ch - phase * CPP) * 64;
        const __nv_bfloat16* As = (phase < 2) ? Ahi : Alo;
        const __nv_bfloat16* Bs = (phase == 1) ? Blo : Bhi;
        uint32_t ab = sA_u + buf * ABUF;
        uint32_t bb = sB_u + buf * BBUF;
#pragma unroll
        for (int i = 0; i < 4; i++)
            cp_async16(ab + sa_t + i * 16, As + aoff + kc + i * 8);
#pragma unroll
        for (int i = 0; i < 4; i++)
            cp_async16(bb + sb_t + i * 16, Bs + boff + kc * ND + i * 8);
    };

    issue(0, 0);
    cp_commit();

    for (int ch = 0; ch < NC; ch++) {
        int cur = ch & 1;
        if (ch + 1 < NC) {
            issue(ch + 1, cur ^ 1);
            cp_commit();
            cp_wait<1>();
        } else {
            cp_wait<0>();
        }
        __syncthreads();

        uint32_t ab = sA_u + cur * ABUF;
        uint32_t bb = sB_u + cur * BBUF;
#pragma unroll
        for (int ks = 0; ks < 4; ks++) {
            uint32_t a[4][4], b[4][2];
#pragma unroll
            for (int mi = 0; mi < 4; mi++) {
                uint32_t addr = ab +
                    (uint32_t)((wm + mi * 16 + lrow) * APAD + ks * 16 + lsel * 8) * 2;
                ldsm_x4(a[mi][0], a[mi][1], a[mi][2], a[mi][3], addr);
            }
#pragma unroll
            for (int p = 0; p < 2; p++) {
                uint32_t r0, r1, r2, r3;
                uint32_t addr = bb +
                    (uint32_t)((ks * 16 + (bg & 1) * 8 + bL) * BPAD +
                               wn + p * 16 + (bg >> 1) * 8) * 2;
                ldsm_x4_t(r0, r1, r2, r3, addr);
                b[p * 2 + 0][0] = r0; b[p * 2 + 0][1] = r1;
                b[p * 2 + 1][0] = r2; b[p * 2 + 1][1] = r3;
            }
#pragma unroll
            for (int mi = 0; mi < 4; mi++)
#pragma unroll
                for (int ni = 0; ni < 4; ni++)
                    mma16816(acc[mi][ni], a[mi], b[ni]);
        }
        __syncthreads();
    }

    // --- epilogue: fp32 stores
    int erow = lane >> 2;
    int ecol = (lane & 3) * 2;
#pragma unroll
    for (int mi = 0; mi < 4; mi++) {
#pragma unroll
        for (int half = 0; half < 2; half++) {
            int r = wm + mi * 16 + erow + half * 8;
            bool ok = GATHER ? (m0 + r < cnt) : true;
            if (!ok) continue;
            long crow = GATHER ? slots[r] : (m0 + r);
            float* dst = C + crow * LDC + n0 + wn + ecol;
#pragma unroll
            for (int ni = 0; ni < 4; ni++) {
                float2 v = make_float2(acc[mi][ni][half * 2 + 0],
                                       acc[mi][ni][half * 2 + 1]);
                *(float2*)(dst + ni * 8) = v;
            }
        }
    }
}

// ---------------------------------------------------------------------------
// SwiGLU + hi/lo split
// ---------------------------------------------------------------------------
__global__ void swiglu_sh_kernel() {
    int i = blockIdx.x * 256 + threadIdx.x;
    int row = i >> 10, col = i & 1023;
    float y = g_u_sh[row * 2048 + col];
    float g = g_u_sh[row * 2048 + 1024 + col];
    float h = y * g / (1.f + expf(-g));
    __nv_bfloat16 hh = __float2bfloat16_rn(h);
    g_hs_hi[i] = hh;
    g_hs_lo[i] = __float2bfloat16_rn(h - __bfloat162float(hh));
}
__global__ void swiglu_rt_kernel() {
    int i = blockIdx.x * 256 + threadIdx.x;
    int row = i >> 9, col = i & 511;
    float y = g_u_rt[row * 1024 + col];
    float g = g_u_rt[row * 1024 + 512 + col];
    float h = y * g / (1.f + expf(-g));
    __nv_bfloat16 hh = __float2bfloat16_rn(h);
    g_h_hi[i] = hh;
    g_h_lo[i] = __float2bfloat16_rn(h - __bfloat162float(hh));
}

// ---------------------------------------------------------------------------
// Combine: out[n,:] += sum_k wt[n*4+k] * y_rt[n*4+k,:]
// ---------------------------------------------------------------------------
__global__ void combine_kernel(float* __restrict__ out) {
    int i = blockIdx.x * 256 + threadIdx.x;
    int n = i >> 8, j = i & 255;
    float4 acc = *(float4*)(out + (size_t)n * C_DIM + j * 4);
#pragma unroll
    for (int k = 0; k < TOPK; k++) {
        int slot = n * TOPK + k;
        float w = d_wt[slot];
        float4 v = *(const float4*)(g_y_rt + (size_t)slot * C_DIM + j * 4);
        acc.x += w * v.x; acc.y += w * v.y; acc.z += w * v.z; acc.w += w * v.w;
    }
    *(float4*)(out + (size_t)n * C_DIM + j * 4) = acc;
}

// ---------------------------------------------------------------------------
// Launch
// ---------------------------------------------------------------------------
#define GEMM_SMEM (2 * 128 * APAD * 2 + 2 * 64 * BPAD * 2 + 512)

extern "C" void kernel_launch(void* const* d_in, const int* in_sizes, int n_in,
                              void* d_out, int out_size) {
    const float* x     = (const float*)d_in[0];
    const float* gw    = (const float*)d_in[1];
    const float* gb    = (const float*)d_in[2];
    const float* sh_gw = (const float*)d_in[3];
    const float* sh_dw = (const float*)d_in[4];
    const float* ex_gw = (const float*)d_in[5];
    const float* ex_dw = (const float*)d_in[6];
    float* out = (float*)d_out;

    cudaFuncSetAttribute(mma_gemm<1024, 2048, 2048, 0, false>,
                         cudaFuncAttributeMaxDynamicSharedMemorySize, GEMM_SMEM);
    cudaFuncSetAttribute(mma_gemm<1024, 1024, 1024, 0, false>,
                         cudaFuncAttributeMaxDynamicSharedMemorySize, GEMM_SMEM);
    cudaFuncSetAttribute(mma_gemm<1024, 1024, 1024, 2, true>,
                         cudaFuncAttributeMaxDynamicSharedMemorySize, GEMM_SMEM);
    cudaFuncSetAttribute(mma_gemm<512, 1024, 1024, 0, true>,
                         cudaFuncAttributeMaxDynamicSharedMemorySize, GEMM_SMEM);

    void *p_xh, *p_xl, *p_hsh, *p_hsl, *p_ush, *p_urt, *p_hh, *p_hl, *p_yrt;
    void *p_sgh, *p_sgl, *p_sdh, *p_sdl, *p_egh, *p_egl, *p_edh, *p_edl;
    cudaGetSymbolAddress(&p_xh, g_x_hi);   cudaGetSymbolAddress(&p_xl, g_x_lo);
    cudaGetSymbolAddress(&p_hsh, g_hs_hi); cudaGetSymbolAddress(&p_hsl, g_hs_lo);
    cudaGetSymbolAddress(&p_ush, g_u_sh);  cudaGetSymbolAddress(&p_urt, g_u_rt);
    cudaGetSymbolAddress(&p_hh, g_h_hi);   cudaGetSymbolAddress(&p_hl, g_h_lo);
    cudaGetSymbolAddress(&p_yrt, g_y_rt);
    cudaGetSymbolAddress(&p_sgh, g_sgw_hi); cudaGetSymbolAddress(&p_sgl, g_sgw_lo);
    cudaGetSymbolAddress(&p_sdh, g_sdw_hi); cudaGetSymbolAddress(&p_sdl, g_sdw_lo);
    cudaGetSymbolAddress(&p_egh, g_egw_hi); cudaGetSymbolAddress(&p_egl, g_egw_lo);
    cudaGetSymbolAddress(&p_edh, g_edw_hi); cudaGetSymbolAddress(&p_edl, g_edw_lo);

    zero_cnt_kernel<<<1, 32>>>();
    gate_kernel<<<N_TOK, 32>>>(x, gw, gb);

    // streaming hi/lo splits (no transpose: weights stay [K,N])
    split_kernel<<<(N_TOK * C_DIM) / 1024, 256>>>(
        (const float4*)x, (uint2*)p_xh, (uint2*)p_xl);
    split_kernel<<<(C_DIM * 2 * HS_SH) / 1024, 256>>>(
        (const float4*)sh_gw, (uint2*)p_sgh, (uint2*)p_sgl);
    split_kernel<<<(HS_SH * C_DIM) / 1024, 256>>>(
        (const float4*)sh_dw, (uint2*)p_sdh, (uint2*)p_sdl);
    split_kernel<<<(E_NUM * C_DIM * 2 * H_RT) / 1024, 256>>>(
        (const float4*)ex_gw, (uint2*)p_egh, (uint2*)p_egl);
    split_kernel<<<(E_NUM * H_RT * C_DIM) / 1024, 256>>>(
        (const float4*)ex_dw, (uint2*)p_edh, (uint2*)p_edl);

    // shared expert
    mma_gemm<1024, 2048, 2048, 0, false><<<dim3(16, 16, 1), 256, GEMM_SMEM>>>(
        (const __nv_bfloat16*)p_xh, (const __nv_bfloat16*)p_xl,
        (const __nv_bfloat16*)p_sgh, (const __nv_bfloat16*)p_sgl, (float*)p_ush);
    swiglu_sh_kernel<<<(N_TOK * HS_SH) / 256, 256>>>();
    mma_gemm<1024, 1024, 1024, 0, false><<<dim3(16, 8, 1), 256, GEMM_SMEM>>>(
        (const __nv_bfloat16*)p_hsh, (const __nv_bfloat16*)p_hsl,
        (const __nv_bfloat16*)p_sdh, (const __nv_bfloat16*)p_sdl, out);

    // routed experts
    mma_gemm<1024, 1024, 1024, 2, true><<<dim3(16, 8, E_NUM), 256, GEMM_SMEM>>>(
        (const __nv_bfloat16*)p_xh, (const __nv_bfloat16*)p_xl,
        (const __nv_bfloat16*)p_egh, (const __nv_bfloat16*)p_egl, (float*)p_urt);
    swiglu_rt_kernel<<<(NPAIR * H_RT) / 256, 256>>>();
    mma_gemm<512, 1024, 1024, 0, true><<<dim3(16, 8, E_NUM), 256, GEMM_SMEM>>>(
        (const __nv_bfloat16*)p_hh, (const __nv_bfloat16*)p_hl,
        (const __nv_bfloat16*)p_edh, (const __nv_bfloat16*)p_edl, (float*)p_yrt);
    combine_kernel<<<(N_TOK * 256) / 256, 256>>>(out);
}

// round 7
// speedup vs baseline: 1.7206x; 1.7206x over previous
#include <cuda_runtime.h>
#include <cuda_bf16.h>
#include <math.h>
#include <stdint.h>

#define N_TOK 2048
#define C_DIM 1024
#define E_NUM 32
#define TOPK  4
#define H_RT  512
#define HS_SH 1024
#define NPAIR (N_TOK * TOPK)   // 8192

// ---------------------------------------------------------------------------
// Baseline-ISA helpers (ptxas target is sm_103 — tcgen05 unavailable)
// ---------------------------------------------------------------------------
__device__ __forceinline__ uint32_t smem_to_u32(const void* p) {
    uint32_t a;
    asm("{ .reg .u64 t; cvta.to.shared.u64 t, %1; cvt.u32.u64 %0, t; }" : "=r"(a) : "l"(p));
    return a;
}
__device__ __forceinline__ void cp_async16(uint32_t smem_dst, const void* gsrc) {
    asm volatile("cp.async.cg.shared.global [%0], [%1], 16;"
                 :: "r"(smem_dst), "l"(gsrc) : "memory");
}
__device__ __forceinline__ void cp_commit() {
    asm volatile("cp.async.commit_group;" ::: "memory");
}
template <int N>
__device__ __forceinline__ void cp_wait() {
    asm volatile("cp.async.wait_group %0;" :: "n"(N) : "memory");
}
__device__ __forceinline__ void ldsm_x4(uint32_t& r0, uint32_t& r1, uint32_t& r2,
                                        uint32_t& r3, uint32_t addr) {
    asm volatile("ldmatrix.sync.aligned.m8n8.x4.shared.b16 {%0,%1,%2,%3}, [%4];"
                 : "=r"(r0), "=r"(r1), "=r"(r2), "=r"(r3) : "r"(addr));
}
__device__ __forceinline__ void mma16816(float* c, const uint32_t* a, const uint32_t* b) {
    asm volatile("mma.sync.aligned.m16n8k16.row.col.f32.bf16.bf16.f32 "
                 "{%0,%1,%2,%3}, {%4,%5,%6,%7}, {%8,%9}, {%0,%1,%2,%3};"
                 : "+f"(c[0]), "+f"(c[1]), "+f"(c[2]), "+f"(c[3])
                 : "r"(a[0]), "r"(a[1]), "r"(a[2]), "r"(a[3]), "r"(b[0]), "r"(b[1]));
}

// ---------------------------------------------------------------------------
// Scratch: weights transposed to [N,K] bf16 hi/lo (K-major for ldmatrix)
// ---------------------------------------------------------------------------
__device__ __nv_bfloat16 g_x_hi [N_TOK * C_DIM];
__device__ __nv_bfloat16 g_x_lo [N_TOK * C_DIM];
__device__ float         g_u_sh [N_TOK * 2 * HS_SH];
__device__ __nv_bfloat16 g_hs_hi[N_TOK * HS_SH];
__device__ __nv_bfloat16 g_hs_lo[N_TOK * HS_SH];
__device__ float         g_u_rt [NPAIR * 2 * H_RT];
__device__ __nv_bfloat16 g_h_hi [NPAIR * H_RT];
__device__ __nv_bfloat16 g_h_lo [NPAIR * H_RT];
__device__ float         g_y_rt [NPAIR * C_DIM];
__device__ __nv_bfloat16 g_sgw_hi[2 * HS_SH * C_DIM];
__device__ __nv_bfloat16 g_sgw_lo[2 * HS_SH * C_DIM];
__device__ __nv_bfloat16 g_sdw_hi[C_DIM * HS_SH];
__device__ __nv_bfloat16 g_sdw_lo[C_DIM * HS_SH];
__device__ __nv_bfloat16 g_egw_hi[E_NUM * 2 * H_RT * C_DIM];
__device__ __nv_bfloat16 g_egw_lo[E_NUM * 2 * H_RT * C_DIM];
__device__ __nv_bfloat16 g_edw_hi[E_NUM * C_DIM * H_RT];
__device__ __nv_bfloat16 g_edw_lo[E_NUM * C_DIM * H_RT];
__device__ int   d_cnt [E_NUM];
__device__ int   d_slot[E_NUM * N_TOK];
__device__ float d_wt  [NPAIR];

__global__ void zero_cnt_kernel() {
    if (threadIdx.x < E_NUM) d_cnt[threadIdx.x] = 0;
}

// ---------------------------------------------------------------------------
// Gating (verified correct since R1)
// ---------------------------------------------------------------------------
__global__ void gate_kernel(const float* __restrict__ x,
                            const float* __restrict__ gw,
                            const float* __restrict__ gb) {
    int n = blockIdx.x;
    int e = threadIdx.x;
    const float* xr = x + n * C_DIM;
    float acc = 0.f;
#pragma unroll 8
    for (int c = 0; c < C_DIM; c++)
        acc = fmaf(xr[c], gw[c * E_NUM + e], acc);
    float s = 1.f / (1.f + expf(-acc));
    __shared__ float sc[E_NUM];
    sc[e] = s;
    __syncwarp();
    if (e == 0) {
        float sb[E_NUM];
#pragma unroll
        for (int i = 0; i < E_NUM; i++) sb[i] = sc[i] + gb[i];
        int idx[TOPK];
        float wsum = 0.f;
#pragma unroll
        for (int k = 0; k < TOPK; k++) {
            int best = 0; float bv = -1e30f;
            for (int i = 0; i < E_NUM; i++)
                if (sb[i] > bv) { bv = sb[i]; best = i; }
            sb[best] = -2e30f;
            idx[k] = best;
            wsum += sc[best];
        }
        float inv = 1.f / wsum;
#pragma unroll
        for (int k = 0; k < TOPK; k++) {
            int ee = idx[k];
            d_wt[n * TOPK + k] = sc[ee] * inv;
            int pos = atomicAdd(&d_cnt[ee], 1);
            d_slot[ee * N_TOK + pos] = n * TOPK + k;
        }
    }
}

// ---------------------------------------------------------------------------
// Streaming fp32 -> bf16 hi/lo split (for activations x; proven in R5)
// ---------------------------------------------------------------------------
__global__ void split_kernel(const float4* __restrict__ src,
                             uint2* __restrict__ hi, uint2* __restrict__ lo) {
    int i = blockIdx.x * 256 + threadIdx.x;
    float4 v = src[i];
    __nv_bfloat16 h0 = __float2bfloat16_rn(v.x);
    __nv_bfloat16 h1 = __float2bfloat16_rn(v.y);
    __nv_bfloat16 h2 = __float2bfloat16_rn(v.z);
    __nv_bfloat16 h3 = __float2bfloat16_rn(v.w);
    __nv_bfloat16 l0 = __float2bfloat16_rn(v.x - __bfloat162float(h0));
    __nv_bfloat16 l1 = __float2bfloat16_rn(v.y - __bfloat162float(h1));
    __nv_bfloat16 l2 = __float2bfloat16_rn(v.z - __bfloat162float(h2));
    __nv_bfloat16 l3 = __float2bfloat16_rn(v.w - __bfloat162float(h3));
    __nv_bfloat162 hp0(h0, h1), hp1(h2, h3), lp0(l0, l1), lp1(l2, l3);
    hi[i] = make_uint2(*(uint32_t*)&hp0, *(uint32_t*)&hp1);
    lo[i] = make_uint2(*(uint32_t*)&lp0, *(uint32_t*)&lp1);
}

// ---------------------------------------------------------------------------
// Transpose + hi/lo convert: W[KD,ND] fp32 (batched over z) -> Wt[ND,KD] bf16
// (proven in R4)
// ---------------------------------------------------------------------------
template <int KD, int ND>
__global__ void transpose_convert(const float* __restrict__ W,
                                  __nv_bfloat16* __restrict__ hi,
                                  __nv_bfloat16* __restrict__ lo) {
    int b = blockIdx.z;
    const float* Wb = W + (size_t)b * KD * ND;
    __nv_bfloat16* hb = hi + (size_t)b * KD * ND;
    __nv_bfloat16* lb = lo + (size_t)b * KD * ND;
    __shared__ float ts[32][33];
    int n0 = blockIdx.x * 32, k0 = blockIdx.y * 32;
    int tx = threadIdx.x, ty = threadIdx.y;
#pragma unroll
    for (int j = 0; j < 4; j++)
        ts[ty + 8 * j][tx] = Wb[(size_t)(k0 + ty + 8 * j) * ND + n0 + tx];
    __syncthreads();
#pragma unroll
    for (int j = 0; j < 4; j++) {
        int n = n0 + ty + 8 * j;
        float v = ts[tx][ty + 8 * j];
        __nv_bfloat16 h = __float2bfloat16_rn(v);
        hb[(size_t)n * KD + k0 + tx] = h;
        lb[(size_t)n * KD + k0 + tx] = __float2bfloat16_rn(v - __bfloat162float(h));
    }
}

// ---------------------------------------------------------------------------
// FUSED bf16x3 GEMM via mma.sync.m16n8k16 (R4 inner-loop geometry).
//   C = (Ahi+Alo)[M,K] @ (Bhi+Blo)[N,K]^T  computed in ONE K-sweep:
//   per k16 fragment set {ahi, alo, bhi, blo}: acc += ahi*bhi + ahi*blo + alo*bhi
// Block 128x128, BK=32, 8 warps (2M x 4N), 64x32 per warp, double-buffered.
// smem rows padded to 40 bf16 (80B) -> conflict-free ldmatrix (R4-proven).
// GATHER: A rows / C rows via per-expert slot lists (blockIdx.z = expert).
// ---------------------------------------------------------------------------
#define PADK 40
#define TBUF (128 * PADK)           // elements per tile buffer

template <int K_DIM, int LDC, int ASHIFT, bool GATHER>
__global__ void __launch_bounds__(256, 1) mma_gemm(
    const __nv_bfloat16* __restrict__ Ahi, const __nv_bfloat16* __restrict__ Alo,
    const __nv_bfloat16* __restrict__ Bhi, const __nv_bfloat16* __restrict__ Blo,
    float* __restrict__ C)
{
    extern __shared__ __align__(16) char smem[];
    // layout: [stage][array] with array in {Ah, Al, Bh, Bl}
    __nv_bfloat16* sbase = (__nv_bfloat16*)smem;
    int* slots = (int*)(smem + 2 * 4 * TBUF * 2);

    const int NC = K_DIM / 32;

    int t    = threadIdx.x;
    int wid  = t >> 5, lane = t & 31;
    int e    = GATHER ? blockIdx.z : 0;
    int cnt  = GATHER ? d_cnt[e] : (1 << 30);
    int m0   = blockIdx.x * 128;
    if (GATHER && m0 >= cnt) return;
    int n0   = blockIdx.y * 128;

    if (GATHER && t < 128) {
        int m = m0 + t;
        slots[t] = (m < cnt) ? d_slot[e * N_TOK + m] : 0;
    }
    __syncthreads();

    // --- loader geometry (R4): rows lr0 and lr0+64, 16B chunk at k=lc
    int lr0 = t >> 2;
    int lc  = (t & 3) * 8;
    int ga0 = GATHER ? (slots[lr0]      >> ASHIFT) : (m0 + lr0);
    int ga1 = GATHER ? (slots[lr0 + 64] >> ASHIFT) : (m0 + lr0 + 64);
    long aoff0 = (long)ga0 * K_DIM + lc;
    long aoff1 = (long)ga1 * K_DIM + lc;
    long bbase = (long)e * LDC * K_DIM;
    long boff0 = bbase + (long)(n0 + lr0)      * K_DIM + lc;
    long boff1 = bbase + (long)(n0 + lr0 + 64) * K_DIM + lc;

    uint32_t su = smem_to_u32(sbase);
    const uint32_t BUFB = TBUF * 2;          // bytes per tile buffer
    uint32_t da0 = (uint32_t)(lr0 * PADK + lc) * 2;
    uint32_t da1 = (uint32_t)((lr0 + 64) * PADK + lc) * 2;

    // --- mma geometry (R4)
    int wm = (wid >> 2) * 64;
    int wn = (wid & 3) * 32;
    float acc[4][4][4];
#pragma unroll
    for (int i = 0; i < 4; i++)
#pragma unroll
        for (int j = 0; j < 4; j++)
#pragma unroll
            for (int r = 0; r < 4; r++) acc[i][j][r] = 0.f;

    int lrow = lane & 15;
    int lsel = lane >> 4;

    auto issue = [&](int ch, int buf) {
        long koff = (long)ch * 32;
        uint32_t st = su + buf * 4 * BUFB;
        cp_async16(st + 0 * BUFB + da0, Ahi + aoff0 + koff);
        cp_async16(st + 0 * BUFB + da1, Ahi + aoff1 + koff);
        cp_async16(st + 1 * BUFB + da0, Alo + aoff0 + koff);
        cp_async16(st + 1 * BUFB + da1, Alo + aoff1 + koff);
        cp_async16(st + 2 * BUFB + da0, Bhi + boff0 + koff);
        cp_async16(st + 2 * BUFB + da1, Bhi + boff1 + koff);
        cp_async16(st + 3 * BUFB + da0, Blo + boff0 + koff);
        cp_async16(st + 3 * BUFB + da1, Blo + boff1 + koff);
    };

    issue(0, 0);
    cp_commit();

    for (int ch = 0; ch < NC; ch++) {
        int cur = ch & 1;
        if (ch + 1 < NC) {
            issue(ch + 1, cur ^ 1);
            cp_commit();
            cp_wait<1>();
        } else {
            cp_wait<0>();
        }
        __syncthreads();

        uint32_t st = su + cur * 4 * BUFB;
#pragma unroll
        for (int s = 0; s < 2; s++) {
            int kc = s * 2 + lsel;                    // 16B chunk within row
            uint32_t ah[4][4], al[4][4], bh[4][2], bl[4][2];
#pragma unroll
            for (int mi = 0; mi < 4; mi++) {
                uint32_t off = (uint32_t)((wm + mi * 16 + lrow) * PADK + kc * 8) * 2;
                ldsm_x4(ah[mi][0], ah[mi][1], ah[mi][2], ah[mi][3], st + 0 * BUFB + off);
                ldsm_x4(al[mi][0], al[mi][1], al[mi][2], al[mi][3], st + 1 * BUFB + off);
            }
#pragma unroll
            for (int p = 0; p < 2; p++) {
                uint32_t off = (uint32_t)((wn + p * 16 + lrow) * PADK + kc * 8) * 2;
                uint32_t r0, r1, r2, r3;
                ldsm_x4(r0, r1, r2, r3, st + 2 * BUFB + off);
                bh[p * 2 + 0][0] = r0; bh[p * 2 + 1][0] = r1;
                bh[p * 2 + 0][1] = r2; bh[p * 2 + 1][1] = r3;
                ldsm_x4(r0, r1, r2, r3, st + 3 * BUFB + off);
                bl[p * 2 + 0][0] = r0; bl[p * 2 + 1][0] = r1;
                bl[p * 2 + 0][1] = r2; bl[p * 2 + 1][1] = r3;
            }
#pragma unroll
            for (int mi = 0; mi < 4; mi++)
#pragma unroll
                for (int ni = 0; ni < 4; ni++) {
                    mma16816(acc[mi][ni], ah[mi], bh[ni]);
                    mma16816(acc[mi][ni], ah[mi], bl[ni]);
                    mma16816(acc[mi][ni], al[mi], bh[ni]);
                }
        }
        __syncthreads();
    }

    // --- epilogue: fp32 stores (R4)
    int erow = lane >> 2;
    int ecol = (lane & 3) * 2;
#pragma unroll
    for (int mi = 0; mi < 4; mi++) {
#pragma unroll
        for (int half = 0; half < 2; half++) {
            int r = wm + mi * 16 + erow + half * 8;
            bool ok = GATHER ? (m0 + r < cnt) : true;
            if (!ok) continue;
            long crow = GATHER ? slots[r] : (m0 + r);
            float* dst = C + crow * LDC + n0 + wn + ecol;
#pragma unroll
            for (int ni = 0; ni < 4; ni++) {
                float2 v = make_float2(acc[mi][ni][half * 2 + 0],
                                       acc[mi][ni][half * 2 + 1]);
                *(float2*)(dst + ni * 8) = v;
            }
        }
    }
}

// ---------------------------------------------------------------------------
// SwiGLU + hi/lo split
// ---------------------------------------------------------------------------
__global__ void swiglu_sh_kernel() {
    int i = blockIdx.x * 256 + threadIdx.x;
    int row = i >> 10, col = i & 1023;
    float y = g_u_sh[row * 2048 + col];
    float g = g_u_sh[row * 2048 + 1024 + col];
    float h = y * g / (1.f + expf(-g));
    __nv_bfloat16 hh = __float2bfloat16_rn(h);
    g_hs_hi[i] = hh;
    g_hs_lo[i] = __float2bfloat16_rn(h - __bfloat162float(hh));
}
__global__ void swiglu_rt_kernel() {
    int i = blockIdx.x * 256 + threadIdx.x;
    int row = i >> 9, col = i & 511;
    float y = g_u_rt[row * 1024 + col];
    float g = g_u_rt[row * 1024 + 512 + col];
    float h = y * g / (1.f + expf(-g));
    __nv_bfloat16 hh = __float2bfloat16_rn(h);
    g_h_hi[i] = hh;
    g_h_lo[i] = __float2bfloat16_rn(h - __bfloat162float(hh));
}

// ---------------------------------------------------------------------------
// Combine: out[n,:] += sum_k wt[n*4+k] * y_rt[n*4+k,:]
// ---------------------------------------------------------------------------
__global__ void combine_kernel(float* __restrict__ out) {
    int i = blockIdx.x * 256 + threadIdx.x;
    int n = i >> 8, j = i & 255;
    float4 acc = *(float4*)(out + (size_t)n * C_DIM + j * 4);
#pragma unroll
    for (int k = 0; k < TOPK; k++) {
        int slot = n * TOPK + k;
        float w = d_wt[slot];
        float4 v = *(const float4*)(g_y_rt + (size_t)slot * C_DIM + j * 4);
        acc.x += w * v.x; acc.y += w * v.y; acc.z += w * v.z; acc.w += w * v.w;
    }
    *(float4*)(out + (size_t)n * C_DIM + j * 4) = acc;
}

// ---------------------------------------------------------------------------
// Launch
// ---------------------------------------------------------------------------
#define GEMM_SMEM (2 * 4 * TBUF * 2 + 512)   // 82432 bytes

extern "C" void kernel_launch(void* const* d_in, const int* in_sizes, int n_in,
                              void* d_out, int out_size) {
    const float* x     = (const float*)d_in[0];
    const float* gw    = (const float*)d_in[1];
    const float* gb    = (const float*)d_in[2];
    const float* sh_gw = (const float*)d_in[3];
    const float* sh_dw = (const float*)d_in[4];
    const float* ex_gw = (const float*)d_in[5];
    const float* ex_dw = (const float*)d_in[6];
    float* out = (float*)d_out;

    cudaFuncSetAttribute(mma_gemm<1024, 2048, 0, false>,
                         cudaFuncAttributeMaxDynamicSharedMemorySize, GEMM_SMEM);
    cudaFuncSetAttribute(mma_gemm<1024, 1024, 0, false>,
                         cudaFuncAttributeMaxDynamicSharedMemorySize, GEMM_SMEM);
    cudaFuncSetAttribute(mma_gemm<1024, 1024, 2, true>,
                         cudaFuncAttributeMaxDynamicSharedMemorySize, GEMM_SMEM);
    cudaFuncSetAttribute(mma_gemm<512, 1024, 0, true>,
                         cudaFuncAttributeMaxDynamicSharedMemorySize, GEMM_SMEM);

    void *p_xh, *p_xl, *p_hsh, *p_hsl, *p_ush, *p_urt, *p_hh, *p_hl, *p_yrt;
    void *p_sgh, *p_sgl, *p_sdh, *p_sdl, *p_egh, *p_egl, *p_edh, *p_edl;
    cudaGetSymbolAddress(&p_xh, g_x_hi);   cudaGetSymbolAddress(&p_xl, g_x_lo);
    cudaGetSymbolAddress(&p_hsh, g_hs_hi); cudaGetSymbolAddress(&p_hsl, g_hs_lo);
    cudaGetSymbolAddress(&p_ush, g_u_sh);  cudaGetSymbolAddress(&p_urt, g_u_rt);
    cudaGetSymbolAddress(&p_hh, g_h_hi);   cudaGetSymbolAddress(&p_hl, g_h_lo);
    cudaGetSymbolAddress(&p_yrt, g_y_rt);
    cudaGetSymbolAddress(&p_sgh, g_sgw_hi); cudaGetSymbolAddress(&p_sgl, g_sgw_lo);
    cudaGetSymbolAddress(&p_sdh, g_sdw_hi); cudaGetSymbolAddress(&p_sdl, g_sdw_lo);
    cudaGetSymbolAddress(&p_egh, g_egw_hi); cudaGetSymbolAddress(&p_egl, g_egw_lo);
    cudaGetSymbolAddress(&p_edh, g_edw_hi); cudaGetSymbolAddress(&p_edl, g_edw_lo);

    zero_cnt_kernel<<<1, 32>>>();
    gate_kernel<<<N_TOK, 32>>>(x, gw, gb);
    split_kernel<<<(N_TOK * C_DIM) / 1024, 256>>>(
        (const float4*)x, (uint2*)p_xh, (uint2*)p_xl);

    dim3 tb(32, 8);
    transpose_convert<1024, 2048><<<dim3(2048 / 32, 1024 / 32, 1), tb>>>(
        sh_gw, (__nv_bfloat16*)p_sgh, (__nv_bfloat16*)p_sgl);
    transpose_convert<1024, 1024><<<dim3(1024 / 32, 1024 / 32, 1), tb>>>(
        sh_dw, (__nv_bfloat16*)p_sdh, (__nv_bfloat16*)p_sdl);
    transpose_convert<1024, 1024><<<dim3(1024 / 32, 1024 / 32, E_NUM), tb>>>(
        ex_gw, (__nv_bfloat16*)p_egh, (__nv_bfloat16*)p_egl);
    transpose_convert<512, 1024><<<dim3(1024 / 32, 512 / 32, E_NUM), tb>>>(
        ex_dw, (__nv_bfloat16*)p_edh, (__nv_bfloat16*)p_edl);

    // shared expert
    mma_gemm<1024, 2048, 0, false><<<dim3(16, 16, 1), 256, GEMM_SMEM>>>(
        (const __nv_bfloat16*)p_xh, (const __nv_bfloat16*)p_xl,
        (const __nv_bfloat16*)p_sgh, (const __nv_bfloat16*)p_sgl, (float*)p_ush);
    swiglu_sh_kernel<<<(N_TOK * HS_SH) / 256, 256>>>();
    mma_gemm<1024, 1024, 0, false><<<dim3(16, 8, 1), 256, GEMM_SMEM>>>(
        (const __nv_bfloat16*)p_hsh, (const __nv_bfloat16*)p_hsl,
        (const __nv_bfloat16*)p_sdh, (const __nv_bfloat16*)p_sdl, out);

    // routed experts
    mma_gemm<1024, 1024, 2, true><<<dim3(16, 8, E_NUM), 256, GEMM_SMEM>>>(
        (const __nv_bfloat16*)p_xh, (const __nv_bfloat16*)p_xl,
        (const __nv_bfloat16*)p_egh, (const __nv_bfloat16*)p_egl, (float*)p_urt);
    swiglu_rt_kernel<<<(NPAIR * H_RT) / 256, 256>>>();
    mma_gemm<512, 1024, 0, true><<<dim3(16, 8, E_NUM), 256, GEMM_SMEM>>>(
        (const __nv_bfloat16*)p_hh, (const __nv_bfloat16*)p_hl,
        (const __nv_bfloat16*)p_edh, (const __nv_bfloat16*)p_edl, (float*)p_yrt);
    combine_kernel<<<(N_TOK * 256) / 256, 256>>>(out);
}